// round 16
// baseline (speedup 1.0000x reference)
#include <cuda_runtime.h>
#include <cuda_fp16.h>
#include <cstdint>

#define Bb 2
#define Hh 12
#define Ll 2048
#define Dd 768
#define DK 64
#define L2E 1.4426950408889634f
#define MA_ON  (-11.541560327111707f)   // -8 * log2(e)
#define MA_OFF (-1.0e9f)

// ---------------------------------------------------------------------------
// global scratch (all planes fp16; q pre-scaled by 0.125*log2e)
// ---------------------------------------------------------------------------
__device__ uint32_t g_qh[Bb*Hh*Ll*32];                      // proj q out (x0.125*l2e)
__device__ uint32_t g_kh[Bb*Hh*Ll*32];                      // proj k out
__device__ uint32_t g_wh[2][Hh*64*384];                     // [qk][h*64+n][k2]
__device__ uint32_t g_ah[2][4096*384];                      // [qk][row][k2]
__device__ uint32_t g_vth[Bb*Hh*64*1024];                   // [bh*64+d][n2]
__device__ float g_maskf[Bb*Ll];                            // mask ? -8*l2e : -1e9
__device__ float g_pi[Bb*Hh*Ll];

// ---------------------------------------------------------------------------
// helpers
// ---------------------------------------------------------------------------
__device__ __forceinline__ uint32_t pack2(float x, float y) {
    __half2 hh = __floats2half2_rn(x, y);
    return *(uint32_t*)&hh;
}
__device__ __forceinline__ float ex2f(float x) {
    float r;
    asm("ex2.approx.f32 %0, %1;" : "=f"(r) : "f"(x));
    return r;
}

__device__ __forceinline__ void mma16(float d[4], uint32_t a0, uint32_t a1, uint32_t a2,
                                      uint32_t a3, uint32_t b0, uint32_t b1) {
    asm("mma.sync.aligned.m16n8k16.row.col.f32.f16.f16.f32 "
        "{%0,%1,%2,%3},{%4,%5,%6,%7},{%8,%9},{%0,%1,%2,%3};\n"
        : "+f"(d[0]), "+f"(d[1]), "+f"(d[2]), "+f"(d[3])
        : "r"(a0), "r"(a1), "r"(a2), "r"(a3), "r"(b0), "r"(b1));
}

__device__ __forceinline__ uint32_t s2u(const void* p) {
    return (uint32_t)__cvta_generic_to_shared(p);
}
#define LDSM4(r0,r1,r2,r3,addr) \
    asm volatile("ldmatrix.sync.aligned.m8n8.x4.shared.b16 {%0,%1,%2,%3}, [%4];" \
                 : "=r"(r0), "=r"(r1), "=r"(r2), "=r"(r3) : "r"(addr))
#define CP16(dst, src) asm volatile("cp.async.cg.shared.global [%0], [%1], 16;\n" :: "r"(dst), "l"(src))
#define CPCOMMIT() asm volatile("cp.async.commit_group;\n" ::: "memory")
#define CPWAIT1()  asm volatile("cp.async.wait_group 1;\n" ::: "memory")
#define CPWAIT0()  asm volatile("cp.async.wait_group 0;\n" ::: "memory")

// ---------------------------------------------------------------------------
// prep kernels
// ---------------------------------------------------------------------------
__global__ __launch_bounds__(256) void prep_w_kernel(
    const float* __restrict__ Wq, const float* __restrict__ Wk,
    const int* __restrict__ mask)
{
    int idx = blockIdx.x * 256 + threadIdx.x;
    if (idx < Bb * Ll)
        g_maskf[idx] = mask[idx] ? MA_ON : MA_OFF;
    int qk = idx >= (Hh*64*384);
    int r = idx - qk * (Hh*64*384);
    int col = r / 384;
    int k2 = r % 384;
    const float* W = qk ? Wk : Wq;
    g_wh[qk][r] = pack2(W[(size_t)(2*k2) * Dd + col], W[(size_t)(2*k2+1) * Dd + col]);
}

__global__ __launch_bounds__(256) void prep_a_kernel(
    const float* __restrict__ query, const float* __restrict__ key)
{
    int idx = blockIdx.x * 256 + threadIdx.x;
    int qk = idx >= (4096*384);
    int r = idx - qk * (4096*384);
    int row = r / 384;
    int k2  = r % 384;
    const float* src = qk ? key : query;
    float2 f = *(const float2*)&src[(size_t)row * Dd + 2*k2];
    g_ah[qk][r] = pack2(f.x, f.y);
}

// V transposed: g_vth[bh*64 + d][n2] = half2(V[2n2][d], V[2n2+1][d])
__global__ __launch_bounds__(256) void prep_v_kernel(const float* __restrict__ query)
{
    __shared__ uint32_t th[64][33];
    const int tile = blockIdx.x;
    const int bh = blockIdx.y;
    const int b = bh / Hh, h = bh % Hh;
    const int n20 = tile * 32;
    const int tid = threadIdx.x;
    #pragma unroll
    for (int i = 0; i < 8; i++) {
        int lin = tid + 256 * i;
        int n2l = lin >> 6;
        int d = lin & 63;
        const float* q0 = &query[(size_t)(b * Ll + 2*(n20 + n2l)) * Dd + h * DK + d];
        th[d][n2l] = pack2(q0[0], q0[Dd]);
    }
    __syncthreads();
    #pragma unroll
    for (int i = 0; i < 8; i++) {
        int lin = tid + 256 * i;
        int d = lin >> 5;
        int n2l = lin & 31;
        g_vth[(size_t)(bh * 64 + d) * 1024 + n20 + n2l] = th[d][n2l];
    }
}

// ---------------------------------------------------------------------------
// Projection GEMM: 128 rows x 128 cols (2 heads) per block, 256 threads,
// pure fp16, k-tile 64, double-buffered cp.async. q scaled by 0.125*l2e.
// ---------------------------------------------------------------------------
#define PJ_SET 9216   // u32 per stage: Ah 4608 | Wh 4608
#define PROJ_SMEM (2 * PJ_SET * 4)

__global__ __launch_bounds__(256, 2) void proj_mma_kernel(
    const float* __restrict__ bq, const float* __restrict__ bk)
{
    extern __shared__ uint32_t psm[];
    const int qk = blockIdx.z;
    const int tid = threadIdx.x;
    const int w = tid >> 5, lane = tid & 31, g = lane >> 2, t = lane & 3;
    const int rowg = w >> 1, colg = w & 1;
    const int rb0 = rowg * 32;
    const int row0 = blockIdx.x * 128;
    const int hp = blockIdx.y;

    const uint32_t* Agh = g_ah[qk];
    const uint32_t* Wgh = &g_wh[qk][(size_t)hp * 128 * 384];
    const float* bias = qk ? bk : bq;

    const int mA = tid >> 1, kbA = (tid & 1) * 16;

    const int lm = lane >> 3, lr = lane & 7;
    const int loffA = ((lm & 1) * 8 + lr) * 36 + (lm >> 1) * 4;
    const int loffB = ((lm >> 1) * 8 + lr) * 36 + (lm & 1) * 4;

    auto stagep = [&](int kb) {
        uint32_t* S = psm + (kb & 1) * PJ_SET;
        const int koff = kb * 32 + kbA;
        const uint32_t* sa = &Agh[(size_t)(row0 + mA) * 384 + koff];
        const uint32_t* sw = &Wgh[(size_t)mA * 384 + koff];
        #pragma unroll
        for (int i = 0; i < 4; i++) {
            CP16(s2u(&S[mA*36 + kbA + i*4]),        sa + i*4);
            CP16(s2u(&S[4608 + mA*36 + kbA + i*4]), sw + i*4);
        }
        CPCOMMIT();
    };

    stagep(0);
    float acc0[8][4] = {};
    float acc1[8][4] = {};

    #pragma unroll 1
    for (int kb = 0; kb < 12; kb++) {
        if (kb < 11) { stagep(kb + 1); CPWAIT1(); } else { CPWAIT0(); }
        __syncthreads();
        uint32_t sbase = s2u(psm) + ((kb & 1) * PJ_SET) * 4;
        uint32_t a0h = sbase + (rb0*36 + loffA) * 4;
        uint32_t a1h = a0h + 16*36*4;
        uint32_t wb  = sbase + (4608 + colg*64*36 + loffB) * 4;
        #pragma unroll
        for (int j = 0; j < 4; j++) {
            uint32_t p0h0,p0h1,p0h2,p0h3, p1h0,p1h1,p1h2,p1h3;
            LDSM4(p0h0,p0h1,p0h2,p0h3, a0h + j*32);
            LDSM4(p1h0,p1h1,p1h2,p1h3, a1h + j*32);
            #pragma unroll
            for (int p = 0; p < 4; p++) {
                uint32_t wh0, wh1, wh2, wh3;
                LDSM4(wh0, wh1, wh2, wh3, wb + (p*576 + j*8)*4);
                mma16(acc0[2*p],   p0h0,p0h1,p0h2,p0h3, wh0, wh1);
                mma16(acc0[2*p+1], p0h0,p0h1,p0h2,p0h3, wh2, wh3);
                mma16(acc1[2*p],   p1h0,p1h1,p1h2,p1h3, wh0, wh1);
                mma16(acc1[2*p+1], p1h0,p1h1,p1h2,p1h3, wh2, wh3);
            }
        }
        __syncthreads();
    }

    const int hglob = hp * 2 + colg;
    const float* bp = &bias[hglob * 64];
    uint32_t* outp = qk ? g_kh : g_qh;
    const float osc = qk ? 1.0f : (0.125f * L2E);  // fold 1/sqrt(dk)*log2e into q
    #pragma unroll
    for (int rb2 = 0; rb2 < 2; rb2++) {
        float (*acc)[4] = rb2 ? acc1 : acc0;
        #pragma unroll
        for (int half = 0; half < 2; half++) {
            int row = row0 + rb0 + rb2*16 + g + half*8;
            int b_ = row >> 11, l = row & (Ll - 1);
            size_t base = ((size_t)(b_ * Hh + hglob) * Ll + l) * 32;
            #pragma unroll
            for (int jn = 0; jn < 8; jn++) {
                float2 bb = *(const float2*)&bp[jn*8 + 2*t];
                outp[base + jn*4 + t] =
                    pack2((acc[jn][2*half] + bb.x) * osc,
                          (acc[jn][2*half + 1] + bb.y) * osc);
            }
        }
    }
}

// ---------------------------------------------------------------------------
// mu (= pi) kernel
// ---------------------------------------------------------------------------
__global__ __launch_bounds__(256) void mu_kernel(
    const float* __restrict__ query, const int* __restrict__ mask,
    const float* __restrict__ w_mu, const float* __restrict__ b_mu)
{
    const int h = blockIdx.x, b = blockIdx.y;
    const int tid = threadIdx.x;
    __shared__ float wmu[64];
    __shared__ float red[8];
    if (tid < 64) wmu[tid] = w_mu[tid];
    __syncthreads();
    const float bmu = b_mu[0];

    float lg[8];
    float lmax = -1e30f;
    #pragma unroll
    for (int j = 0; j < 8; j++) {
        int l = tid + j * 256;
        const float* sp = &query[((size_t)b * Ll + l) * Dd + h * DK];
        float dm = 0.0f;
        #pragma unroll
        for (int d = 0; d < 64; d += 4) {
            float4 s4 = *(const float4*)&sp[d];
            dm += s4.x * wmu[d] + s4.y * wmu[d+1] + s4.z * wmu[d+2] + s4.w * wmu[d+3];
        }
        float v = dm + bmu;
        if (mask[b * Ll + l] == 0) v = -1e9f;
        lg[j] = v;
        lmax = fmaxf(lmax, v);
    }
    {
        int wi = tid >> 5, lane = tid & 31;
        #pragma unroll
        for (int o = 16; o; o >>= 1) lmax = fmaxf(lmax, __shfl_xor_sync(~0u, lmax, o));
        if (lane == 0) red[wi] = lmax;
        __syncthreads();
        if (wi == 0) {
            float r = (lane < 8) ? red[lane] : -1e30f;
            #pragma unroll
            for (int o = 16; o; o >>= 1) r = fmaxf(r, __shfl_xor_sync(~0u, r, o));
            if (lane == 0) red[0] = r;
        }
        __syncthreads();
        lmax = red[0];
        __syncthreads();
    }
    float lsum = 0.0f;
    #pragma unroll
    for (int j = 0; j < 8; j++) { lg[j] = __expf(lg[j] - lmax); lsum += lg[j]; }
    {
        int wi = tid >> 5, lane = tid & 31;
        #pragma unroll
        for (int o = 16; o; o >>= 1) lsum += __shfl_xor_sync(~0u, lsum, o);
        if (lane == 0) red[wi] = lsum;
        __syncthreads();
        if (wi == 0) {
            float r = (lane < 8) ? red[lane] : 0.0f;
            #pragma unroll
            for (int o = 16; o; o >>= 1) r += __shfl_xor_sync(~0u, r, o);
            if (lane == 0) red[0] = r;
        }
        __syncthreads();
        lsum = red[0];
    }
    float inv = 1.0f / lsum;
    #pragma unroll
    for (int j = 0; j < 8; j++)
        g_pi[((size_t)b * Hh + h) * Ll + tid + j * 256] = lg[j] * inv;
}

// ---------------------------------------------------------------------------
// Attention: 128-row tiles, 256 threads (8 warps x 16 rows), fp16.
// Base-2 fixed-offset softmax: q carries 0.125*l2e; short folded via FFMA;
// mask+offset folded into additive g_maskf plane. P = ex2(arg) in (0, ~0.2].
// ---------------------------------------------------------------------------
#define LS 68
#define STAGE_F 13376   // floats: SBuf 128*68=8704 | K 2304 | V 2304 | maskf 64
#define ATTN_SMEM (2 * STAGE_F * 4)

__global__ __launch_bounds__(256, 2) void attn_mma_kernel(
    const float* __restrict__ query, const float* __restrict__ shortb,
    const float* __restrict__ bias_m, float* __restrict__ out)
{
    extern __shared__ float smb[];

    const int tid = threadIdx.x;
    const int w = tid >> 5, lane = tid & 31;
    const int g = lane >> 2, t = lane & 3;
    const int rw = w * 16;
    const int m0 = blockIdx.x * 128;
    const int h = blockIdx.y, b = blockIdx.z;
    const size_t bh = (size_t)b * Hh + h;
    const float* sp = shortb + (bh * Ll + m0) * Ll;

    const int lm = lane >> 3, lr = lane & 7;
    const int loffB = ((lm >> 1) * 8 + lr) * 36 + (lm & 1) * 4;

    const int rS = tid >> 2, sS = (tid & 3) * 8;

    auto stageA = [&](int n0, int bi) {
        float* SB = smb + bi * STAGE_F;
        uint32_t* K = (uint32_t*)(SB + 8704);
        uint32_t* V = K + 2304;
        float* M = (float*)(V + 2304);
        #pragma unroll
        for (int it = 0; it < 8; it++) {
            int lin = tid + it * 256, row = lin >> 4, c4 = (lin & 15) * 4;
            CP16(s2u(&SB[row * LS + c4]), &sp[(size_t)row * Ll + n0 + c4]);
        }
        const uint32_t* skh = &g_kh[(bh * Ll + n0 + rS) * 32 + sS];
        const uint32_t* svh = &g_vth[(bh * 64 + rS) * 1024 + (n0 >> 1) + sS];
        CP16(s2u(&K[rS*36 + sS]),     skh);
        CP16(s2u(&K[rS*36 + sS + 4]), skh + 4);
        CP16(s2u(&V[rS*36 + sS]),     svh);
        CP16(s2u(&V[rS*36 + sS + 4]), svh + 4);
        if (tid < 16) CP16(s2u(&M[tid * 4]), &g_maskf[b * Ll + n0 + tid * 4]);
        CPCOMMIT();
    };

    // ---- Q fragments (pre-scaled by 0.125*l2e) ----
    uint32_t qh[16];
    {
        const uint32_t* qhp  = &g_qh[(bh * Ll + m0 + rw + g) * 32];
        const uint32_t* qhp8 = qhp + 8 * 32;
        #pragma unroll
        for (int j = 0; j < 4; j++) {
            qh[j*4 + 0] = qhp [8*j + t];
            qh[j*4 + 1] = qhp8[8*j + t];
            qh[j*4 + 2] = qhp [8*j + t + 4];
            qh[j*4 + 3] = qhp8[8*j + t + 4];
        }
    }

    stageA(0, 0);
    stageA(64, 1);
    CPWAIT1();
    __syncthreads();

    float accO[8][4] = {};
    float lrow[2] = {0.0f, 0.0f};

    #pragma unroll 1
    for (int nb = 0; nb < 32; nb++) {
        const int bi = nb & 1;
        float* SB = smb + bi * STAGE_F;
        const float* SBw = SB + rw * LS;
        uint32_t kbase = s2u(SB + 8704) + loffB * 4;
        uint32_t vbase = kbase + 2304 * 4;
        const float* Mc = (const float*)(SB + 8704 + 4608);

        // ---- S = Q K^T (already in log2 domain) ----
        float s[8][4] = {};
        #pragma unroll
        for (int j = 0; j < 4; j++) {
            uint32_t kf[16];
            #pragma unroll
            for (int p = 0; p < 4; p++)
                LDSM4(kf[p*4], kf[p*4+1], kf[p*4+2], kf[p*4+3],
                      kbase + (p*576 + j*8)*4);
            #pragma unroll
            for (int p = 0; p < 4; p++) {
                mma16(s[2*p],   qh[j*4], qh[j*4+1], qh[j*4+2], qh[j*4+3], kf[p*4],   kf[p*4+1]);
                mma16(s[2*p+1], qh[j*4], qh[j*4+1], qh[j*4+2], qh[j*4+3], kf[p*4+2], kf[p*4+3]);
            }
        }

        // ---- P = 2^( qk*l2e + short*l2e + maskf ), local row-sum ----
        #pragma unroll
        for (int jn = 0; jn < 8; jn++) {
            int c0 = jn * 8 + 2 * t;
            float2 ma = *(const float2*)&Mc[c0];
            float2 sh0 = *(const float2*)&SBw[(g)     * LS + c0];
            float2 sh1 = *(const float2*)&SBw[(g + 8) * LS + c0];
            s[jn][0] = ex2f(fmaf(sh0.x, L2E, s[jn][0]) + ma.x);
            s[jn][1] = ex2f(fmaf(sh0.y, L2E, s[jn][1]) + ma.y);
            s[jn][2] = ex2f(fmaf(sh1.x, L2E, s[jn][2]) + ma.x);
            s[jn][3] = ex2f(fmaf(sh1.y, L2E, s[jn][3]) + ma.y);
            lrow[0] += s[jn][0] + s[jn][1];
            lrow[1] += s[jn][2] + s[jn][3];
        }

        // ---- accO += P V ----
        #pragma unroll
        for (int j = 0; j < 4; j++) {
            uint32_t ph0 = pack2(s[2*j][0],   s[2*j][1]);
            uint32_t ph1 = pack2(s[2*j][2],   s[2*j][3]);
            uint32_t ph2 = pack2(s[2*j+1][0], s[2*j+1][1]);
            uint32_t ph3 = pack2(s[2*j+1][2], s[2*j+1][3]);
            #pragma unroll
            for (int p = 0; p < 4; p++) {
                uint32_t vh0, vh1, vh2, vh3;
                LDSM4(vh0, vh1, vh2, vh3, vbase + (p*576 + j*8)*4);
                mma16(accO[2*p],   ph0, ph1, ph2, ph3, vh0, vh1);
                mma16(accO[2*p+1], ph0, ph1, ph2, ph3, vh2, vh3);
            }
        }

        // ---- rotate buffers ----
        __syncthreads();
        if (nb < 31) {
            int n2 = (nb + 2 < 32 ? nb + 2 : 31) * 64;
            stageA(n2, bi);
            CPWAIT1();
            __syncthreads();
        }
    }

    // ---- finalize row sums across the quad ----
    #pragma unroll
    for (int half = 0; half < 2; half++) {
        lrow[half] += __shfl_xor_sync(0xffffffffu, lrow[half], 1);
        lrow[half] += __shfl_xor_sync(0xffffffffu, lrow[half], 2);
    }

    // ---- fused epilogue ----
    const float bm = bias_m[0];
    #pragma unroll
    for (int half = 0; half < 2; half++) {
        const int r0 = half * 2;
        int row = m0 + rw + g + half * 8;
        float piv = g_pi[bh * Ll + row] * 0.2f;
        float inv = 0.8f / lrow[half];
        #pragma unroll
        for (int jd = 0; jd < 8; jd++) {
            int c = jd * 8 + 2 * t;
            float2 sq = *(const float2*)&query[((size_t)b * Ll + row) * Dd + h * DK + c];
            float2 o;
            o.x = accO[jd][r0]     * inv + piv * sq.x + bm;
            o.y = accO[jd][r0 + 1] * inv + piv * sq.y + bm;
            *(float2*)&out[(bh * Ll + row) * DK + c] = o;
        }
    }
}

// ---------------------------------------------------------------------------
extern "C" void kernel_launch(void* const* d_in, const int* in_sizes, int n_in,
                              void* d_out, int out_size)
{
    const float* query  = (const float*)d_in[0];
    const float* key    = (const float*)d_in[1];
    const float* shortb = (const float*)d_in[2];
    const int*   mask   = (const int*)d_in[4];
    const float* Wq     = (const float*)d_in[5];
    const float* bq     = (const float*)d_in[6];
    const float* Wk     = (const float*)d_in[7];
    const float* bk     = (const float*)d_in[8];
    const float* w_mu   = (const float*)d_in[9];
    const float* b_mu   = (const float*)d_in[10];
    const float* bias_m = (const float*)d_in[11];
    float* out = (float*)d_out;

    cudaFuncSetAttribute(proj_mma_kernel, cudaFuncAttributeMaxDynamicSharedMemorySize, PROJ_SMEM);
    cudaFuncSetAttribute(attn_mma_kernel, cudaFuncAttributeMaxDynamicSharedMemorySize, ATTN_SMEM);

    prep_w_kernel<<<2304, 256>>>(Wq, Wk, mask);
    prep_a_kernel<<<12288, 256>>>(query, key);
    prep_v_kernel<<<dim3(32, 24), 256>>>(query);
    proj_mma_kernel<<<dim3(32, 6, 2), 256, PROJ_SMEM>>>(bq, bk);
    mu_kernel<<<dim3(12, 2), 256>>>(query, mask, w_mu, b_mu);
    attn_mma_kernel<<<dim3(16, 12, 2), 256, ATTN_SMEM>>>(query, shortb, bias_m, out);
}

// round 17
// speedup vs baseline: 1.0647x; 1.0647x over previous
#include <cuda_runtime.h>
#include <cuda_fp16.h>
#include <cstdint>

#define Bb 2
#define Hh 12
#define Ll 2048
#define Dd 768
#define DK 64
#define NEGV (-1000000000.0f)
#define SOFT_OFF 8.0f   // fixed softmax base: keeps fp16 P in normal range

// ---------------------------------------------------------------------------
// global scratch (all planes fp16; q pre-scaled by 1/8 — exact in fp16)
// ---------------------------------------------------------------------------
__device__ uint32_t g_qh[Bb*Hh*Ll*32];                      // proj q out (x0.125)
__device__ uint32_t g_kh[Bb*Hh*Ll*32];                      // proj k out
__device__ uint32_t g_wh[2][Hh*64*384];                     // [qk][h*64+n][k2]
__device__ uint32_t g_ah[2][4096*384];                      // [qk][row][k2]
__device__ uint32_t g_vth[Bb*Hh*64*1024];                   // [bh*64+d][n2]
__device__ float g_pi[Bb*Hh*Ll];

// ---------------------------------------------------------------------------
// helpers
// ---------------------------------------------------------------------------
__device__ __forceinline__ uint32_t pack2(float x, float y) {
    __half2 hh = __floats2half2_rn(x, y);
    return *(uint32_t*)&hh;
}

__device__ __forceinline__ void mma16(float d[4], uint32_t a0, uint32_t a1, uint32_t a2,
                                      uint32_t a3, uint32_t b0, uint32_t b1) {
    asm("mma.sync.aligned.m16n8k16.row.col.f32.f16.f16.f32 "
        "{%0,%1,%2,%3},{%4,%5,%6,%7},{%8,%9},{%0,%1,%2,%3};\n"
        : "+f"(d[0]), "+f"(d[1]), "+f"(d[2]), "+f"(d[3])
        : "r"(a0), "r"(a1), "r"(a2), "r"(a3), "r"(b0), "r"(b1));
}

__device__ __forceinline__ uint32_t s2u(const void* p) {
    return (uint32_t)__cvta_generic_to_shared(p);
}
#define LDSM4(r0,r1,r2,r3,addr) \
    asm volatile("ldmatrix.sync.aligned.m8n8.x4.shared.b16 {%0,%1,%2,%3}, [%4];" \
                 : "=r"(r0), "=r"(r1), "=r"(r2), "=r"(r3) : "r"(addr))
#define CP16(dst, src) asm volatile("cp.async.cg.shared.global [%0], [%1], 16;\n" :: "r"(dst), "l"(src))
#define CPCOMMIT() asm volatile("cp.async.commit_group;\n" ::: "memory")
#define CPWAIT1()  asm volatile("cp.async.wait_group 1;\n" ::: "memory")
#define CPWAIT0()  asm volatile("cp.async.wait_group 0;\n" ::: "memory")

// ---------------------------------------------------------------------------
// fused prep kernel: blocks [0,2304) W-split, [2304,14592) A-split,
// [14592,15360) V-transpose. 256 threads each.
// ---------------------------------------------------------------------------
__global__ __launch_bounds__(256) void prep_kernel(
    const float* __restrict__ Wq, const float* __restrict__ Wk,
    const float* __restrict__ query, const float* __restrict__ key)
{
    const int blk = blockIdx.x;
    const int tid = threadIdx.x;

    if (blk < 2304) {
        // ---- W planes ----
        int idx = blk * 256 + tid;
        int qk = idx >= (Hh*64*384);
        int r = idx - qk * (Hh*64*384);
        int col = r / 384;
        int k2 = r % 384;
        const float* W = qk ? Wk : Wq;
        g_wh[qk][r] = pack2(W[(size_t)(2*k2) * Dd + col], W[(size_t)(2*k2+1) * Dd + col]);
    } else if (blk < 14592) {
        // ---- A planes (query/key rows) ----
        int idx = (blk - 2304) * 256 + tid;
        int qk = idx >= (4096*384);
        int r = idx - qk * (4096*384);
        int row = r / 384;
        int k2  = r % 384;
        const float* src = qk ? key : query;
        float2 f = *(const float2*)&src[(size_t)row * Dd + 2*k2];
        g_ah[qk][r] = pack2(f.x, f.y);
    } else {
        // ---- V transpose: g_vth[bh*64+d][n2] = half2(V[2n2][d], V[2n2+1][d]) ----
        __shared__ uint32_t th[64][33];
        int vb = blk - 14592;          // 0..767
        int tile = vb & 31;            // n2-tile
        int bh = vb >> 5;              // 0..23
        int b = bh / Hh, h = bh % Hh;
        int n20 = tile * 32;
        #pragma unroll
        for (int i = 0; i < 8; i++) {
            int lin = tid + 256 * i;
            int n2l = lin >> 6;
            int d = lin & 63;
            const float* q0 = &query[(size_t)(b * Ll + 2*(n20 + n2l)) * Dd + h * DK + d];
            th[d][n2l] = pack2(q0[0], q0[Dd]);
        }
        __syncthreads();
        #pragma unroll
        for (int i = 0; i < 8; i++) {
            int lin = tid + 256 * i;
            int d = lin >> 5;
            int n2l = lin & 31;
            g_vth[(size_t)(bh * 64 + d) * 1024 + n20 + n2l] = th[d][n2l];
        }
    }
}

// ---------------------------------------------------------------------------
// Projection GEMM: 128 rows x 128 cols (2 heads) per block, 256 threads,
// pure fp16, k-tile 64, double-buffered cp.async. q scaled by 0.125 (exact).
// ---------------------------------------------------------------------------
#define PJ_SET 9216   // u32 per stage: Ah 4608 | Wh 4608
#define PROJ_SMEM (2 * PJ_SET * 4)

__global__ __launch_bounds__(256, 2) void proj_mma_kernel(
    const float* __restrict__ bq, const float* __restrict__ bk)
{
    extern __shared__ uint32_t psm[];
    const int qk = blockIdx.z;
    const int tid = threadIdx.x;
    const int w = tid >> 5, lane = tid & 31, g = lane >> 2, t = lane & 3;
    const int rowg = w >> 1, colg = w & 1;
    const int rb0 = rowg * 32;
    const int row0 = blockIdx.x * 128;
    const int hp = blockIdx.y;

    const uint32_t* Agh = g_ah[qk];
    const uint32_t* Wgh = &g_wh[qk][(size_t)hp * 128 * 384];
    const float* bias = qk ? bk : bq;

    const int mA = tid >> 1, kbA = (tid & 1) * 16;

    const int lm = lane >> 3, lr = lane & 7;
    const int loffA = ((lm & 1) * 8 + lr) * 36 + (lm >> 1) * 4;
    const int loffB = ((lm >> 1) * 8 + lr) * 36 + (lm & 1) * 4;

    auto stagep = [&](int kb) {
        uint32_t* S = psm + (kb & 1) * PJ_SET;
        const int koff = kb * 32 + kbA;
        const uint32_t* sa = &Agh[(size_t)(row0 + mA) * 384 + koff];
        const uint32_t* sw = &Wgh[(size_t)mA * 384 + koff];
        #pragma unroll
        for (int i = 0; i < 4; i++) {
            CP16(s2u(&S[mA*36 + kbA + i*4]),        sa + i*4);
            CP16(s2u(&S[4608 + mA*36 + kbA + i*4]), sw + i*4);
        }
        CPCOMMIT();
    };

    stagep(0);
    float acc0[8][4] = {};
    float acc1[8][4] = {};

    #pragma unroll 1
    for (int kb = 0; kb < 12; kb++) {
        if (kb < 11) { stagep(kb + 1); CPWAIT1(); } else { CPWAIT0(); }
        __syncthreads();
        uint32_t sbase = s2u(psm) + ((kb & 1) * PJ_SET) * 4;
        uint32_t a0h = sbase + (rb0*36 + loffA) * 4;
        uint32_t a1h = a0h + 16*36*4;
        uint32_t wb  = sbase + (4608 + colg*64*36 + loffB) * 4;
        #pragma unroll
        for (int j = 0; j < 4; j++) {
            uint32_t p0h0,p0h1,p0h2,p0h3, p1h0,p1h1,p1h2,p1h3;
            LDSM4(p0h0,p0h1,p0h2,p0h3, a0h + j*32);
            LDSM4(p1h0,p1h1,p1h2,p1h3, a1h + j*32);
            #pragma unroll
            for (int p = 0; p < 4; p++) {
                uint32_t wh0, wh1, wh2, wh3;
                LDSM4(wh0, wh1, wh2, wh3, wb + (p*576 + j*8)*4);
                mma16(acc0[2*p],   p0h0,p0h1,p0h2,p0h3, wh0, wh1);
                mma16(acc0[2*p+1], p0h0,p0h1,p0h2,p0h3, wh2, wh3);
                mma16(acc1[2*p],   p1h0,p1h1,p1h2,p1h3, wh0, wh1);
                mma16(acc1[2*p+1], p1h0,p1h1,p1h2,p1h3, wh2, wh3);
            }
        }
        __syncthreads();
    }

    const int hglob = hp * 2 + colg;
    const float* bp = &bias[hglob * 64];
    uint32_t* outp = qk ? g_kh : g_qh;
    const float osc = qk ? 1.0f : 0.125f;   // fold 1/sqrt(dk) into q (exact pow2)
    #pragma unroll
    for (int rb2 = 0; rb2 < 2; rb2++) {
        float (*acc)[4] = rb2 ? acc1 : acc0;
        #pragma unroll
        for (int half = 0; half < 2; half++) {
            int row = row0 + rb0 + rb2*16 + g + half*8;
            int b_ = row >> 11, l = row & (Ll - 1);
            size_t base = ((size_t)(b_ * Hh + hglob) * Ll + l) * 32;
            #pragma unroll
            for (int jn = 0; jn < 8; jn++) {
                float2 bb = *(const float2*)&bp[jn*8 + 2*t];
                outp[base + jn*4 + t] =
                    pack2((acc[jn][2*half] + bb.x) * osc,
                          (acc[jn][2*half + 1] + bb.y) * osc);
            }
        }
    }
}

// ---------------------------------------------------------------------------
// mu (= pi) kernel
// ---------------------------------------------------------------------------
__global__ __launch_bounds__(256) void mu_kernel(
    const float* __restrict__ query, const int* __restrict__ mask,
    const float* __restrict__ w_mu, const float* __restrict__ b_mu)
{
    const int h = blockIdx.x, b = blockIdx.y;
    const int tid = threadIdx.x;
    __shared__ float wmu[64];
    __shared__ float red[8];
    if (tid < 64) wmu[tid] = w_mu[tid];
    __syncthreads();
    const float bmu = b_mu[0];

    float lg[8];
    float lmax = -1e30f;
    #pragma unroll
    for (int j = 0; j < 8; j++) {
        int l = tid + j * 256;
        const float* sp = &query[((size_t)b * Ll + l) * Dd + h * DK];
        float dm = 0.0f;
        #pragma unroll
        for (int d = 0; d < 64; d += 4) {
            float4 s4 = *(const float4*)&sp[d];
            dm += s4.x * wmu[d] + s4.y * wmu[d+1] + s4.z * wmu[d+2] + s4.w * wmu[d+3];
        }
        float v = dm + bmu;
        if (mask[b * Ll + l] == 0) v = NEGV;
        lg[j] = v;
        lmax = fmaxf(lmax, v);
    }
    {
        int wi = tid >> 5, lane = tid & 31;
        #pragma unroll
        for (int o = 16; o; o >>= 1) lmax = fmaxf(lmax, __shfl_xor_sync(~0u, lmax, o));
        if (lane == 0) red[wi] = lmax;
        __syncthreads();
        if (wi == 0) {
            float r = (lane < 8) ? red[lane] : -1e30f;
            #pragma unroll
            for (int o = 16; o; o >>= 1) r = fmaxf(r, __shfl_xor_sync(~0u, r, o));
            if (lane == 0) red[0] = r;
        }
        __syncthreads();
        lmax = red[0];
        __syncthreads();
    }
    float lsum = 0.0f;
    #pragma unroll
    for (int j = 0; j < 8; j++) { lg[j] = __expf(lg[j] - lmax); lsum += lg[j]; }
    {
        int wi = tid >> 5, lane = tid & 31;
        #pragma unroll
        for (int o = 16; o; o >>= 1) lsum += __shfl_xor_sync(~0u, lsum, o);
        if (lane == 0) red[wi] = lsum;
        __syncthreads();
        if (wi == 0) {
            float r = (lane < 8) ? red[lane] : 0.0f;
            #pragma unroll
            for (int o = 16; o; o >>= 1) r += __shfl_xor_sync(~0u, r, o);
            if (lane == 0) red[0] = r;
        }
        __syncthreads();
        lsum = red[0];
    }
    float inv = 1.0f / lsum;
    #pragma unroll
    for (int j = 0; j < 8; j++)
        g_pi[((size_t)b * Hh + h) * Ll + tid + j * 256] = lg[j] * inv;
}

// ---------------------------------------------------------------------------
// Attention: 128-row tiles, 256 threads (8 warps x 16 rows), fp16.
// Fixed-base softmax with OFF=8 (fp16-P safe): no running max, no rescale;
// row-sum shuffles deferred to epilogue. Q pre-scaled by 1/8.
// ---------------------------------------------------------------------------
#define LS 68
#define STAGE_F 13376   // floats: SBuf 128*68=8704 | K 2304 | V 2304 | mask 64
#define ATTN_SMEM (2 * STAGE_F * 4)

__global__ __launch_bounds__(256, 2) void attn_mma_kernel(
    const float* __restrict__ query, const float* __restrict__ shortb,
    const int* __restrict__ mask, const float* __restrict__ bias_m,
    float* __restrict__ out)
{
    extern __shared__ float smb[];

    const int tid = threadIdx.x;
    const int w = tid >> 5, lane = tid & 31;
    const int g = lane >> 2, t = lane & 3;
    const int rw = w * 16;
    const int m0 = blockIdx.x * 128;
    const int h = blockIdx.y, b = blockIdx.z;
    const size_t bh = (size_t)b * Hh + h;
    const float* sp = shortb + (bh * Ll + m0) * Ll;

    const int lm = lane >> 3, lr = lane & 7;
    const int loffB = ((lm >> 1) * 8 + lr) * 36 + (lm & 1) * 4;

    const int rS = tid >> 2, sS = (tid & 3) * 8;

    auto stageA = [&](int n0, int bi) {
        float* SB = smb + bi * STAGE_F;
        uint32_t* K = (uint32_t*)(SB + 8704);
        uint32_t* V = K + 2304;
        int* M = (int*)(V + 2304);
        #pragma unroll
        for (int it = 0; it < 8; it++) {
            int lin = tid + it * 256, row = lin >> 4, c4 = (lin & 15) * 4;
            CP16(s2u(&SB[row * LS + c4]), &sp[(size_t)row * Ll + n0 + c4]);
        }
        const uint32_t* skh = &g_kh[(bh * Ll + n0 + rS) * 32 + sS];
        const uint32_t* svh = &g_vth[(bh * 64 + rS) * 1024 + (n0 >> 1) + sS];
        CP16(s2u(&K[rS*36 + sS]),     skh);
        CP16(s2u(&K[rS*36 + sS + 4]), skh + 4);
        CP16(s2u(&V[rS*36 + sS]),     svh);
        CP16(s2u(&V[rS*36 + sS + 4]), svh + 4);
        if (tid < 16) CP16(s2u(&M[tid * 4]), &mask[b * Ll + n0 + tid * 4]);
        CPCOMMIT();
    };

    // ---- Q fragments (pre-scaled by 1/8) ----
    uint32_t qh[16];
    {
        const uint32_t* qhp  = &g_qh[(bh * Ll + m0 + rw + g) * 32];
        const uint32_t* qhp8 = qhp + 8 * 32;
        #pragma unroll
        for (int j = 0; j < 4; j++) {
            qh[j*4 + 0] = qhp [8*j + t];
            qh[j*4 + 1] = qhp8[8*j + t];
            qh[j*4 + 2] = qhp [8*j + t + 4];
            qh[j*4 + 3] = qhp8[8*j + t + 4];
        }
    }

    stageA(0, 0);
    stageA(64, 1);
    CPWAIT1();
    __syncthreads();

    float accO[8][4] = {};
    float lrow[2] = {0.0f, 0.0f};   // thread-local partial row sums

    #pragma unroll 1
    for (int nb = 0; nb < 32; nb++) {
        const int bi = nb & 1;
        float* SB = smb + bi * STAGE_F;
        const float* SBw = SB + rw * LS;
        uint32_t kbase = s2u(SB + 8704) + loffB * 4;
        uint32_t vbase = kbase + 2304 * 4;
        const int* Mc = (const int*)(SB + 8704 + 4608);

        // ---- S = Q K^T ----
        float s[8][4] = {};
        #pragma unroll
        for (int j = 0; j < 4; j++) {
            uint32_t kf[16];
            #pragma unroll
            for (int p = 0; p < 4; p++)
                LDSM4(kf[p*4], kf[p*4+1], kf[p*4+2], kf[p*4+3],
                      kbase + (p*576 + j*8)*4);
            #pragma unroll
            for (int p = 0; p < 4; p++) {
                mma16(s[2*p],   qh[j*4], qh[j*4+1], qh[j*4+2], qh[j*4+3], kf[p*4],   kf[p*4+1]);
                mma16(s[2*p+1], qh[j*4], qh[j*4+1], qh[j*4+2], qh[j*4+3], kf[p*4+2], kf[p*4+3]);
            }
        }

        // ---- mask, +short, exp (fixed base), local row-sum ----
        #pragma unroll
        for (int jn = 0; jn < 8; jn++) {
            int c0 = jn * 8 + 2 * t;
            int2 mk = *(const int2*)&Mc[c0];
            float2 sh0 = *(const float2*)&SBw[(g)     * LS + c0];
            float2 sh1 = *(const float2*)&SBw[(g + 8) * LS + c0];
            s[jn][0] = __expf((mk.x ? s[jn][0] + sh0.x : NEGV) - SOFT_OFF);
            s[jn][1] = __expf((mk.y ? s[jn][1] + sh0.y : NEGV) - SOFT_OFF);
            s[jn][2] = __expf((mk.x ? s[jn][2] + sh1.x : NEGV) - SOFT_OFF);
            s[jn][3] = __expf((mk.y ? s[jn][3] + sh1.y : NEGV) - SOFT_OFF);
            lrow[0] += s[jn][0] + s[jn][1];
            lrow[1] += s[jn][2] + s[jn][3];
        }

        // ---- accO += P V ----
        #pragma unroll
        for (int j = 0; j < 4; j++) {
            uint32_t ph0 = pack2(s[2*j][0],   s[2*j][1]);
            uint32_t ph1 = pack2(s[2*j][2],   s[2*j][3]);
            uint32_t ph2 = pack2(s[2*j+1][0], s[2*j+1][1]);
            uint32_t ph3 = pack2(s[2*j+1][2], s[2*j+1][3]);
            #pragma unroll
            for (int p = 0; p < 4; p++) {
                uint32_t vh0, vh1, vh2, vh3;
                LDSM4(vh0, vh1, vh2, vh3, vbase + (p*576 + j*8)*4);
                mma16(accO[2*p],   ph0, ph1, ph2, ph3, vh0, vh1);
                mma16(accO[2*p+1], ph0, ph1, ph2, ph3, vh2, vh3);
            }
        }

        // ---- rotate buffers ----
        __syncthreads();
        if (nb < 31) {
            int n2 = (nb + 2 < 32 ? nb + 2 : 31) * 64;
            stageA(n2, bi);
            CPWAIT1();
            __syncthreads();
        }
    }

    // ---- finalize row sums across the quad (once, not per chunk) ----
    #pragma unroll
    for (int half = 0; half < 2; half++) {
        lrow[half] += __shfl_xor_sync(0xffffffffu, lrow[half], 1);
        lrow[half] += __shfl_xor_sync(0xffffffffu, lrow[half], 2);
    }

    // ---- fused epilogue ----
    const float bm = bias_m[0];
    #pragma unroll
    for (int half = 0; half < 2; half++) {
        const int r0 = half * 2;
        int row = m0 + rw + g + half * 8;
        float piv = g_pi[bh * Ll + row] * 0.2f;
        float inv = 0.8f / lrow[half];
        #pragma unroll
        for (int jd = 0; jd < 8; jd++) {
            int c = jd * 8 + 2 * t;
            float2 sq = *(const float2*)&query[((size_t)b * Ll + row) * Dd + h * DK + c];
            float2 o;
            o.x = accO[jd][r0]     * inv + piv * sq.x + bm;
            o.y = accO[jd][r0 + 1] * inv + piv * sq.y + bm;
            *(float2*)&out[(bh * Ll + row) * DK + c] = o;
        }
    }
}

// ---------------------------------------------------------------------------
extern "C" void kernel_launch(void* const* d_in, const int* in_sizes, int n_in,
                              void* d_out, int out_size)
{
    const float* query  = (const float*)d_in[0];
    const float* key    = (const float*)d_in[1];
    const float* shortb = (const float*)d_in[2];
    const int*   mask   = (const int*)d_in[4];
    const float* Wq     = (const float*)d_in[5];
    const float* bq     = (const float*)d_in[6];
    const float* Wk     = (const float*)d_in[7];
    const float* bk     = (const float*)d_in[8];
    const float* w_mu   = (const float*)d_in[9];
    const float* b_mu   = (const float*)d_in[10];
    const float* bias_m = (const float*)d_in[11];
    float* out = (float*)d_out;

    cudaFuncSetAttribute(proj_mma_kernel, cudaFuncAttributeMaxDynamicSharedMemorySize, PROJ_SMEM);
    cudaFuncSetAttribute(attn_mma_kernel, cudaFuncAttributeMaxDynamicSharedMemorySize, ATTN_SMEM);

    prep_kernel<<<15360, 256>>>(Wq, Wk, query, key);
    proj_mma_kernel<<<dim3(32, 6, 2), 256, PROJ_SMEM>>>(bq, bk);
    mu_kernel<<<dim3(12, 2), 256>>>(query, mask, w_mu, b_mu);
    attn_mma_kernel<<<dim3(16, 12, 2), 256, ATTN_SMEM>>>(query, shortb, mask, bias_m, out);
}